// round 4
// baseline (speedup 1.0000x reference)
#include <cuda_runtime.h>

#define BB 4
#define SS 2048
#define DD 1024
#define HH 16
#define DHH 64
#define KSTRIDE 68   // padded shared stride for transposed tiles (16B-aligned float4 reads)

// Scratch: Q, K, V, attention-out, each (B,H,S,DH) fp32 = 32MB
__device__ float g_Q[BB*HH*SS*DHH];
__device__ float g_K[BB*HH*SS*DHH];
__device__ float g_V[BB*HH*SS*DHH];
__device__ float g_O[BB*HH*SS*DHH];

// ---------------------------------------------------------------------------
// QKV projection: C[b,h,s,k] = sum_d x[b,s,d] * W[h,d,k]
// grid: (M/64=128, H=16, 3 projections), block: 256 threads, 64x64 C tile
// ---------------------------------------------------------------------------
__global__ __launch_bounds__(256) void qkv_kernel(
    const float* __restrict__ x, const float* __restrict__ Wq,
    const float* __restrict__ Wk, const float* __restrict__ Wv) {
  __shared__ float As[16 * 64];  // [k][m]
  __shared__ float Bs[16 * 64];  // [k][n]
  const int proj = blockIdx.z;
  const int h = blockIdx.y;
  const float* W = (proj == 0 ? Wq : (proj == 1 ? Wk : Wv)) + (size_t)h * DD * DHH;
  float* out = (proj == 0 ? g_Q : (proj == 1 ? g_K : g_V));

  const int tid = threadIdx.x;
  const int tx = tid & 15, ty = tid >> 4;
  const int m0 = blockIdx.x * 64;
  const int arow = tid >> 2, acol = (tid & 3) * 4;   // A tile loader: 64 rows x 16 k
  const int brow = tid >> 4, bcol = (tid & 15) * 4;  // B tile loader: 16 k x 64 n

  float acc[4][4] = {};

  for (int k0 = 0; k0 < DD; k0 += 16) {
    float4 a = *(const float4*)&x[(size_t)(m0 + arow) * DD + k0 + acol];
    As[(acol + 0) * 64 + arow] = a.x;
    As[(acol + 1) * 64 + arow] = a.y;
    As[(acol + 2) * 64 + arow] = a.z;
    As[(acol + 3) * 64 + arow] = a.w;
    *(float4*)&Bs[brow * 64 + bcol] =
        *(const float4*)&W[(size_t)(k0 + brow) * DHH + bcol];
    __syncthreads();
#pragma unroll
    for (int kk = 0; kk < 16; kk++) {
      float4 av = *(const float4*)&As[kk * 64 + ty * 4];
      float4 bv = *(const float4*)&Bs[kk * 64 + tx * 4];
      float ar[4] = {av.x, av.y, av.z, av.w};
      float br[4] = {bv.x, bv.y, bv.z, bv.w};
#pragma unroll
      for (int i = 0; i < 4; i++)
#pragma unroll
        for (int j = 0; j < 4; j++) acc[i][j] += ar[i] * br[j];
    }
    __syncthreads();
  }

#pragma unroll
  for (int i = 0; i < 4; i++) {
    int m = m0 + ty * 4 + i;
    int b = m >> 11, s = m & 2047;
    float4 v = {acc[i][0], acc[i][1], acc[i][2], acc[i][3]};
    *(float4*)&out[(((size_t)(b * HH + h)) * SS + s) * DHH + tx * 4] = v;
  }
}

// ---------------------------------------------------------------------------
// Flash attention: per (q-block of 64 rows, head, batch).
// Online softmax, K^T/Q^T in shared at stride 68.
// grid: (S/64=32, H=16, B=4), block: 256 threads
// dynamic smem: Qt[64*68] + KP[64*68] + Vs[64*64] = 51200 bytes
// ---------------------------------------------------------------------------
__global__ __launch_bounds__(256, 3) void attn_kernel() {
  extern __shared__ float sm[];
  float* Qt = sm;                 // Q^T: Qt[k*68 + r], pre-scaled by 1/8
  float* KP = sm + 64 * KSTRIDE;  // phase 1: K^T [k*68 + c]; phase 2: P [r*64 + c]
  float* Vs = sm + 2 * 64 * KSTRIDE;  // V natural [j*64 + c]

  const int tid = threadIdx.x;
  const int tx = tid & 15, ty = tid >> 4;
  const size_t base = (((size_t)blockIdx.z * HH + blockIdx.y) * SS) * DHH;
  const float* Qp = g_Q + base + (size_t)blockIdx.x * 64 * DHH;
  const float* Kp = g_K + base;
  const float* Vp = g_V + base;

  // Load Q tile transposed + scaled by 1/sqrt(DH)=0.125
  for (int i = tid; i < 64 * 16; i += 256) {
    int r = i >> 4;
    int c4 = (i & 15) * 4;
    float4 v = *(const float4*)&Qp[r * DHH + c4];
    Qt[(c4 + 0) * KSTRIDE + r] = v.x * 0.125f;
    Qt[(c4 + 1) * KSTRIDE + r] = v.y * 0.125f;
    Qt[(c4 + 2) * KSTRIDE + r] = v.z * 0.125f;
    Qt[(c4 + 3) * KSTRIDE + r] = v.w * 0.125f;
  }

  float m_i[4], l_i[4], acc[4][4] = {};
#pragma unroll
  for (int i = 0; i < 4; i++) { m_i[i] = -1e30f; l_i[i] = 0.0f; }

  for (int kb = 0; kb < SS / 64; kb++) {
    __syncthreads();  // previous iteration's P/V reads done (also covers Qt init)
    // Load K tile transposed
    for (int i = tid; i < 64 * 16; i += 256) {
      int r = i >> 4;          // key index within block
      int c4 = (i & 15) * 4;   // head-dim
      float4 v = *(const float4*)&Kp[(size_t)(kb * 64 + r) * DHH + c4];
      KP[(c4 + 0) * KSTRIDE + r] = v.x;
      KP[(c4 + 1) * KSTRIDE + r] = v.y;
      KP[(c4 + 2) * KSTRIDE + r] = v.z;
      KP[(c4 + 3) * KSTRIDE + r] = v.w;
    }
    // Load V tile natural layout
    {
      const float4* vsrc = (const float4*)&Vp[(size_t)kb * 64 * DHH];
      for (int i = tid; i < 64 * 16; i += 256) ((float4*)Vs)[i] = vsrc[i];
    }
    __syncthreads();

    // S = (Q/8) K^T  -- 64x64 tile, 4x4 per thread
    float s[4][4] = {};
#pragma unroll 8
    for (int k = 0; k < 64; k++) {
      float4 qv = *(const float4*)&Qt[k * KSTRIDE + ty * 4];
      float4 kv = *(const float4*)&KP[k * KSTRIDE + tx * 4];
      float qr[4] = {qv.x, qv.y, qv.z, qv.w};
      float kr[4] = {kv.x, kv.y, kv.z, kv.w};
#pragma unroll
      for (int i = 0; i < 4; i++)
#pragma unroll
        for (int j = 0; j < 4; j++) s[i][j] += qr[i] * kr[j];
    }

    // Online softmax update (row stats reduced across the 16 tx lanes)
#pragma unroll
    for (int i = 0; i < 4; i++) {
      float mx = fmaxf(fmaxf(s[i][0], s[i][1]), fmaxf(s[i][2], s[i][3]));
#pragma unroll
      for (int o = 8; o > 0; o >>= 1)
        mx = fmaxf(mx, __shfl_xor_sync(0xffffffffu, mx, o));
      float mn = fmaxf(m_i[i], mx);
      float alpha = __expf(m_i[i] - mn);
      m_i[i] = mn;
      float rs = 0.0f;
#pragma unroll
      for (int j = 0; j < 4; j++) {
        s[i][j] = __expf(s[i][j] - mn);
        rs += s[i][j];
      }
#pragma unroll
      for (int o = 8; o > 0; o >>= 1) rs += __shfl_xor_sync(0xffffffffu, rs, o);
      l_i[i] = l_i[i] * alpha + rs;
#pragma unroll
      for (int j = 0; j < 4; j++) acc[i][j] *= alpha;
    }

    __syncthreads();  // all warps done reading K^T; reuse buffer for P
#pragma unroll
    for (int i = 0; i < 4; i++) {
      float4 pv = {s[i][0], s[i][1], s[i][2], s[i][3]};
      *(float4*)&KP[(ty * 4 + i) * 64 + tx * 4] = pv;
    }
    __syncthreads();

    // O += P @ V
#pragma unroll 8
    for (int jj = 0; jj < 64; jj++) {
      float4 vv = *(const float4*)&Vs[jj * 64 + tx * 4];
      float vr[4] = {vv.x, vv.y, vv.z, vv.w};
      float pr[4];
#pragma unroll
      for (int i = 0; i < 4; i++) pr[i] = KP[(ty * 4 + i) * 64 + jj];
#pragma unroll
      for (int i = 0; i < 4; i++)
#pragma unroll
        for (int j = 0; j < 4; j++) acc[i][j] += pr[i] * vr[j];
    }
  }

  // Normalize and store
  float* Op = g_O + base + (size_t)blockIdx.x * 64 * DHH;
#pragma unroll
  for (int i = 0; i < 4; i++) {
    float inv = 1.0f / l_i[i];
    float4 v = {acc[i][0] * inv, acc[i][1] * inv, acc[i][2] * inv, acc[i][3] * inv};
    *(float4*)&Op[(size_t)(ty * 4 + i) * DHH + tx * 4] = v;
  }
}

// ---------------------------------------------------------------------------
// Output projection: out[b,s,n] = sum_d concat[b,s,d] * Wo[d,n]
// concat(b,s, h*64+kk) = g_O[b,h,s,kk]
// grid: (M/64=128, D/64=16), block: 256 threads
// ---------------------------------------------------------------------------
__global__ __launch_bounds__(256) void proj_kernel(
    const float* __restrict__ Wo, float* __restrict__ out) {
  __shared__ float As[16 * 64];
  __shared__ float Bs[16 * 64];
  const int tid = threadIdx.x;
  const int tx = tid & 15, ty = tid >> 4;
  const int m0 = blockIdx.x * 64, n0 = blockIdx.y * 64;
  const int arow = tid >> 2, acol = (tid & 3) * 4;
  const int brow = tid >> 4, bcol = (tid & 15) * 4;

  const int m = m0 + arow;
  const int b = m >> 11, s = m & 2047;

  float acc[4][4] = {};

  for (int k0 = 0; k0 < DD; k0 += 16) {
    int d = k0 + acol;            // d..d+3 lie within one head (d % 4 == 0, 64 % 16 == 0)
    int hh = d >> 6, kk = d & 63;
    float4 a = *(const float4*)&g_O[(((size_t)(b * HH + hh)) * SS + s) * DHH + kk];
    As[(acol + 0) * 64 + arow] = a.x;
    As[(acol + 1) * 64 + arow] = a.y;
    As[(acol + 2) * 64 + arow] = a.z;
    As[(acol + 3) * 64 + arow] = a.w;
    *(float4*)&Bs[brow * 64 + bcol] =
        *(const float4*)&Wo[(size_t)(k0 + brow) * DD + n0 + bcol];
    __syncthreads();
#pragma unroll
    for (int kk2 = 0; kk2 < 16; kk2++) {
      float4 av = *(const float4*)&As[kk2 * 64 + ty * 4];
      float4 bv = *(const float4*)&Bs[kk2 * 64 + tx * 4];
      float ar[4] = {av.x, av.y, av.z, av.w};
      float br[4] = {bv.x, bv.y, bv.z, bv.w};
#pragma unroll
      for (int i = 0; i < 4; i++)
#pragma unroll
        for (int j = 0; j < 4; j++) acc[i][j] += ar[i] * br[j];
    }
    __syncthreads();
  }

#pragma unroll
  for (int i = 0; i < 4; i++) {
    float4 v = {acc[i][0], acc[i][1], acc[i][2], acc[i][3]};
    *(float4*)&out[(size_t)(m0 + ty * 4 + i) * DD + n0 + tx * 4] = v;
  }
}

// ---------------------------------------------------------------------------
extern "C" void kernel_launch(void* const* d_in, const int* in_sizes, int n_in,
                              void* d_out, int out_size) {
  const float* x  = (const float*)d_in[0];
  const float* Wq = (const float*)d_in[1];
  const float* Wk = (const float*)d_in[2];
  const float* Wv = (const float*)d_in[3];
  const float* Wo = (const float*)d_in[4];
  float* out = (float*)d_out;

  const int attn_smem = (2 * 64 * KSTRIDE + 64 * 64) * (int)sizeof(float);  // 51200
  cudaFuncSetAttribute(attn_kernel, cudaFuncAttributeMaxDynamicSharedMemorySize,
                       attn_smem);

  qkv_kernel<<<dim3(128, HH, 3), 256>>>(x, Wq, Wk, Wv);
  attn_kernel<<<dim3(SS / 64, HH, BB), 256, attn_smem>>>();
  proj_kernel<<<dim3(128, DD / 64), 256>>>(Wo, out);
}

// round 6
// speedup vs baseline: 2.8355x; 2.8355x over previous
#include <cuda_runtime.h>
#include <cstdint>

#define BB 4
#define SS 2048
#define DD 1024
#define HH 16
#define DHH 64

// Scratch: Q, K, V, attention-out, each (B,H,S,DH) fp32 = 32MB
__device__ float g_Q[BB*HH*SS*DHH];
__device__ float g_K[BB*HH*SS*DHH];
__device__ float g_V[BB*HH*SS*DHH];
__device__ float g_O[BB*HH*SS*DHH];

// ---------------------------------------------------------------------------
// tf32 helpers
// ---------------------------------------------------------------------------
__device__ __forceinline__ uint32_t cvt_tf32(float x) {
  uint32_t y;
  asm("cvt.rna.tf32.f32 %0, %1;" : "=r"(y) : "f"(x));
  return y;
}
__device__ __forceinline__ float cvt_tf32f(float x) {
  return __uint_as_float(cvt_tf32(x));
}
__device__ __forceinline__ float4 cvt4(float4 v) {
  return make_float4(cvt_tf32f(v.x), cvt_tf32f(v.y), cvt_tf32f(v.z), cvt_tf32f(v.w));
}

// ldmatrix x4: four 8x8 b16 tiles == one 16x8 tf32 A fragment (a0..a3)
__device__ __forceinline__ void ldsm4(uint32_t a[4], const float* p) {
  uint32_t addr = (uint32_t)__cvta_generic_to_shared(p);
  asm volatile("ldmatrix.sync.aligned.m8n8.x4.shared.b16 {%0,%1,%2,%3}, [%4];"
               : "=r"(a[0]), "=r"(a[1]), "=r"(a[2]), "=r"(a[3]) : "r"(addr));
}
__device__ __forceinline__ void mma8(float c[4], const uint32_t a[4],
                                     uint32_t b0, uint32_t b1) {
  asm volatile(
      "mma.sync.aligned.m16n8k8.row.col.f32.tf32.tf32.f32 "
      "{%0,%1,%2,%3},{%4,%5,%6,%7},{%8,%9},{%0,%1,%2,%3};"
      : "+f"(c[0]), "+f"(c[1]), "+f"(c[2]), "+f"(c[3])
      : "r"(a[0]), "r"(a[1]), "r"(a[2]), "r"(a[3]), "r"(b0), "r"(b1));
}

#define ASTR 36    // A smem row stride (floats): odd 16B-units -> ldmatrix conflict-free
#define BSTR 136   // B smem row stride (floats): (8k+n)%32 bijective -> LDS conflict-free

// ---------------------------------------------------------------------------
// QKV projection, tf32 mma. C tile 128(M) x 128(N = 2 heads).
// grid: (64, 8 head-pairs, 3 projections), block 256 (8 warps: 4M x 2N)
// ---------------------------------------------------------------------------
__global__ __launch_bounds__(256, 2) void qkv_mma(
    const float* __restrict__ x, const float* __restrict__ Wq,
    const float* __restrict__ Wk, const float* __restrict__ Wv) {
  __shared__ __align__(16) float As[128 * ASTR];
  __shared__ __align__(16) float Bs[32 * BSTR];
  const int tid = threadIdx.x, lane = tid & 31, warp = tid >> 5;
  const int wm = warp >> 1, wn = warp & 1;
  const int proj = blockIdx.z, hp = blockIdx.y;
  const int m0 = blockIdx.x * 128;
  const float* W = (proj == 0 ? Wq : (proj == 1 ? Wk : Wv)) + (size_t)hp * 2 * DD * DHH;
  float* out = proj == 0 ? g_Q : (proj == 1 ? g_K : g_V);

  const int arow = tid >> 1, ac0 = (tid & 1) * 16;
  const int bd = warp * 4 + (lane & 3), bc0 = (lane >> 2) * 16;

  float c[2][8][4];
#pragma unroll
  for (int i = 0; i < 2; i++)
#pragma unroll
    for (int j = 0; j < 8; j++)
#pragma unroll
      for (int q = 0; q < 4; q++) c[i][j][q] = 0.f;

  const float* xp = x + (size_t)(m0 + arow) * DD + ac0;

  float4 ast[4], bst[4];
#pragma unroll
  for (int i = 0; i < 4; i++) ast[i] = *(const float4*)(xp + i * 4);
#pragma unroll
  for (int i = 0; i < 4; i++) {
    int col = bc0 + i * 4;
    const float* src = (col < 64) ? (W + (size_t)bd * DHH + col)
                                  : (W + (size_t)DD * DHH + (size_t)bd * DHH + col - 64);
    bst[i] = *(const float4*)src;
  }

  for (int k0 = 0; k0 < DD; k0 += 32) {
    __syncthreads();
#pragma unroll
    for (int i = 0; i < 4; i++)
      *(float4*)&As[arow * ASTR + ac0 + i * 4] = cvt4(ast[i]);
#pragma unroll
    for (int i = 0; i < 4; i++)
      *(float4*)&Bs[bd * BSTR + bc0 + i * 4] = cvt4(bst[i]);
    __syncthreads();

    if (k0 + 32 < DD) {
      const float* xn = xp + k0 + 32;
#pragma unroll
      for (int i = 0; i < 4; i++) ast[i] = *(const float4*)(xn + i * 4);
#pragma unroll
      for (int i = 0; i < 4; i++) {
        int col = bc0 + i * 4;
        const float* src = (col < 64)
            ? (W + (size_t)(k0 + 32 + bd) * DHH + col)
            : (W + (size_t)DD * DHH + (size_t)(k0 + 32 + bd) * DHH + col - 64);
        bst[i] = *(const float4*)src;
      }
    }

#pragma unroll
    for (int ks = 0; ks < 4; ks++) {
      uint32_t a[2][4];
      const int matl = lane >> 3, mj = lane & 7;
      const int acol = ks * 8 + (matl >> 1) * 4;
#pragma unroll
      for (int mt = 0; mt < 2; mt++)
        ldsm4(a[mt], &As[(wm * 32 + mt * 16 + (matl & 1) * 8 + mj) * ASTR + acol]);
      const int brow = ks * 8 + (lane & 3);
#pragma unroll
      for (int nt = 0; nt < 8; nt++) {
        int n = wn * 64 + nt * 8 + (lane >> 2);
        uint32_t b0 = __float_as_uint(Bs[brow * BSTR + n]);
        uint32_t b1 = __float_as_uint(Bs[(brow + 4) * BSTR + n]);
        mma8(c[0][nt], a[0], b0, b1);
        mma8(c[1][nt], a[1], b0, b1);
      }
    }
  }

#pragma unroll
  for (int mt = 0; mt < 2; mt++)
#pragma unroll
    for (int hh = 0; hh < 2; hh++) {
      int row = m0 + wm * 32 + mt * 16 + (lane >> 2) + hh * 8;
      int b = row >> 11, s = row & 2047;
#pragma unroll
      for (int nt = 0; nt < 8; nt++) {
        int col = wn * 64 + nt * 8 + (lane & 3) * 2;
        int head = hp * 2 + (col >> 6), dh = col & 63;
        *(float2*)&out[(((size_t)(b * HH + head)) * SS + s) * DHH + dh] =
            make_float2(c[mt][nt][hh * 2], c[mt][nt][hh * 2 + 1]);
      }
    }
}

// ---------------------------------------------------------------------------
// Flash attention, tf32 mma. Block: 128 q-rows; iterate 64-key blocks.
// 8 warps, each owns 16 COMPLETE q-rows (full 64-key span) -> softmax is
// quad-local (shfl xor 1,2), no cross-warp reduction needed.
// smem: Qs[128][68] + KP[128][68] (K rows 0-63, then P rows 0-127) + Vs[64][72]
// ---------------------------------------------------------------------------
#define QSTR 68
#define PSTR 68
#define VSTR 72

__global__ __launch_bounds__(256, 2) void attn_mma() {
  extern __shared__ __align__(16) float sm[];
  float* Qs = sm;
  float* KP = sm + 128 * QSTR;
  float* Vs = KP + 128 * PSTR;

  const int tid = threadIdx.x, lane = tid & 31, warp = tid >> 5;
  const size_t base = ((size_t)blockIdx.z * HH + blockIdx.y) * SS * DHH;
  const int q0 = blockIdx.x * 128;
  const float* Qp = g_Q + base + (size_t)q0 * DHH;
  const float* Kp = g_K + base;
  const float* Vp = g_V + base;
  float* Op = g_O + base + (size_t)q0 * DHH;

  {  // load Q, scaled by 1/sqrt(64)=0.125, tf32
    int row = tid >> 1, c0 = (tid & 1) * 32;
#pragma unroll
    for (int i = 0; i < 8; i++) {
      float4 v = *(const float4*)&Qp[(size_t)row * DHH + c0 + i * 4];
      *(float4*)&Qs[row * QSTR + c0 + i * 4] =
          make_float4(cvt_tf32f(v.x * 0.125f), cvt_tf32f(v.y * 0.125f),
                      cvt_tf32f(v.z * 0.125f), cvt_tf32f(v.w * 0.125f));
    }
  }

  float o[8][4];
#pragma unroll
  for (int j = 0; j < 8; j++)
#pragma unroll
    for (int q = 0; q < 4; q++) o[j][q] = 0.f;
  float mst[2] = {-1e30f, -1e30f}, lst[2] = {0.f, 0.f};

  const int kvrow = tid >> 2, kvc0 = (tid & 3) * 16;
  float4 kst[4], vst[4];
#pragma unroll
  for (int i = 0; i < 4; i++) {
    kst[i] = *(const float4*)&Kp[(size_t)kvrow * DHH + kvc0 + i * 4];
    vst[i] = *(const float4*)&Vp[(size_t)kvrow * DHH + kvc0 + i * 4];
  }

  const int matl = lane >> 3, mj = lane & 7;

  for (int kb = 0; kb < SS / 64; kb++) {
    __syncthreads();  // prev iteration's P/V reads done (also covers Q load)
#pragma unroll
    for (int i = 0; i < 4; i++) {
      *(float4*)&KP[kvrow * PSTR + kvc0 + i * 4] = cvt4(kst[i]);
      *(float4*)&Vs[kvrow * VSTR + kvc0 + i * 4] = cvt4(vst[i]);
    }
    __syncthreads();
    if (kb + 1 < SS / 64) {
      const float* kn = Kp + (size_t)(kb + 1) * 64 * DHH + (size_t)kvrow * DHH + kvc0;
      const float* vn = Vp + (size_t)(kb + 1) * 64 * DHH + (size_t)kvrow * DHH + kvc0;
#pragma unroll
      for (int i = 0; i < 4; i++) {
        kst[i] = *(const float4*)(kn + i * 4);
        vst[i] = *(const float4*)(vn + i * 4);
      }
    }

    // ---- S = (Q*scale) @ K^T : warp computes its 16 rows x 64 keys ----
    float s[8][4];
#pragma unroll
    for (int j = 0; j < 8; j++)
#pragma unroll
      for (int q = 0; q < 4; q++) s[j][q] = 0.f;

#pragma unroll
    for (int ks = 0; ks < 8; ks++) {
      uint32_t a[4];
      ldsm4(a, &Qs[(warp * 16 + (matl & 1) * 8 + mj) * QSTR + ks * 8 + (matl >> 1) * 4]);
      const int kk = ks * 8 + (lane & 3);
#pragma unroll
      for (int nt = 0; nt < 8; nt++) {
        int key = nt * 8 + (lane >> 2);
        uint32_t b0 = __float_as_uint(KP[key * PSTR + kk]);
        uint32_t b1 = __float_as_uint(KP[key * PSTR + kk + 4]);
        mma8(s[nt], a, b0, b1);
      }
    }

    // ---- online softmax: row r = lane>>2 (+8 for hh=1), cols across lane&3 ----
#pragma unroll
    for (int hh = 0; hh < 2; hh++) {
      float mx = s[0][hh * 2];
#pragma unroll
      for (int nt = 0; nt < 8; nt++) {
        mx = fmaxf(mx, s[nt][hh * 2]);
        mx = fmaxf(mx, s[nt][hh * 2 + 1]);
      }
      mx = fmaxf(mx, __shfl_xor_sync(0xffffffffu, mx, 1));
      mx = fmaxf(mx, __shfl_xor_sync(0xffffffffu, mx, 2));
      float mn = fmaxf(mst[hh], mx);
      float alpha = __expf(mst[hh] - mn);
      mst[hh] = mn;
      float rs = 0.f;
#pragma unroll
      for (int nt = 0; nt < 8; nt++)
#pragma unroll
        for (int q = 0; q < 2; q++) {
          float e = __expf(s[nt][hh * 2 + q] - mn);
          s[nt][hh * 2 + q] = e;
          rs += e;
        }
      rs += __shfl_xor_sync(0xffffffffu, rs, 1);
      rs += __shfl_xor_sync(0xffffffffu, rs, 2);
      lst[hh] = lst[hh] * alpha + rs;
#pragma unroll
      for (int nt = 0; nt < 8; nt++)
#pragma unroll
        for (int q = 0; q < 2; q++) o[nt][hh * 2 + q] *= alpha;
    }

    __syncthreads();  // all warps done reading K from KP
    // ---- write P (tf32) into KP rows 0-127 ----
#pragma unroll
    for (int hh = 0; hh < 2; hh++) {
      int prow = warp * 16 + (lane >> 2) + hh * 8;
#pragma unroll
      for (int nt = 0; nt < 8; nt++) {
        int pcol = nt * 8 + (lane & 3) * 2;
        *(float2*)&KP[prow * PSTR + pcol] = make_float2(
            cvt_tf32f(s[nt][hh * 2]), cvt_tf32f(s[nt][hh * 2 + 1]));
      }
    }
    __syncthreads();

    // ---- O += P @ V : warp-local, reduction over 64 keys ----
#pragma unroll
    for (int ks = 0; ks < 8; ks++) {
      uint32_t a[4];
      ldsm4(a, &KP[(warp * 16 + (matl & 1) * 8 + mj) * PSTR + ks * 8 + (matl >> 1) * 4]);
      const int kk = ks * 8 + (lane & 3);
#pragma unroll
      for (int nt = 0; nt < 8; nt++) {
        int dh = nt * 8 + (lane >> 2);
        uint32_t b0 = __float_as_uint(Vs[kk * VSTR + dh]);
        uint32_t b1 = __float_as_uint(Vs[(kk + 4) * VSTR + dh]);
        mma8(o[nt], a, b0, b1);
      }
    }
  }

  // epilogue: normalize, store
#pragma unroll
  for (int hh = 0; hh < 2; hh++) {
    int row = warp * 16 + (lane >> 2) + hh * 8;
    float inv = 1.f / lst[hh];
#pragma unroll
    for (int nt = 0; nt < 8; nt++) {
      int col = nt * 8 + (lane & 3) * 2;
      *(float2*)&Op[(size_t)row * DHH + col] =
          make_float2(o[nt][hh * 2] * inv, o[nt][hh * 2 + 1] * inv);
    }
  }
}

// ---------------------------------------------------------------------------
// Output projection, tf32 mma: out = concat(O) @ Wo. C tile 128x128.
// grid: (64, 8), block 256
// ---------------------------------------------------------------------------
__global__ __launch_bounds__(256, 2) void proj_mma(
    const float* __restrict__ Wo, float* __restrict__ out) {
  __shared__ __align__(16) float As[128 * ASTR];
  __shared__ __align__(16) float Bs[32 * BSTR];
  const int tid = threadIdx.x, lane = tid & 31, warp = tid >> 5;
  const int wm = warp >> 1, wn = warp & 1;
  const int m0 = blockIdx.x * 128, n0 = blockIdx.y * 128;

  const int arow = tid >> 1, ac0 = (tid & 1) * 16;
  const int bd = warp * 4 + (lane & 3), bc0 = (lane >> 2) * 16;
  const int am = m0 + arow, ab = am >> 11, asq = am & 2047;

  float c[2][8][4];
#pragma unroll
  for (int i = 0; i < 2; i++)
#pragma unroll
    for (int j = 0; j < 8; j++)
#pragma unroll
      for (int q = 0; q < 4; q++) c[i][j][q] = 0.f;

  float4 ast[4], bst[4];
#pragma unroll
  for (int i = 0; i < 4; i++) {
    int d = ac0 + i * 4;
    ast[i] = *(const float4*)&g_O[(((size_t)(ab * HH + (d >> 6))) * SS + asq) * DHH + (d & 63)];
    bst[i] = *(const float4*)&Wo[(size_t)bd * DD + n0 + bc0 + i * 4];
  }

  for (int k0 = 0; k0 < DD; k0 += 32) {
    __syncthreads();
#pragma unroll
    for (int i = 0; i < 4; i++)
      *(float4*)&As[arow * ASTR + ac0 + i * 4] = cvt4(ast[i]);
#pragma unroll
    for (int i = 0; i < 4; i++)
      *(float4*)&Bs[bd * BSTR + bc0 + i * 4] = cvt4(bst[i]);
    __syncthreads();

    if (k0 + 32 < DD) {
#pragma unroll
      for (int i = 0; i < 4; i++) {
        int d = k0 + 32 + ac0 + i * 4;
        ast[i] = *(const float4*)&g_O[(((size_t)(ab * HH + (d >> 6))) * SS + asq) * DHH + (d & 63)];
        bst[i] = *(const float4*)&Wo[(size_t)(k0 + 32 + bd) * DD + n0 + bc0 + i * 4];
      }
    }

#pragma unroll
    for (int ks = 0; ks < 4; ks++) {
      uint32_t a[2][4];
      const int matl = lane >> 3, mj = lane & 7;
      const int acol = ks * 8 + (matl >> 1) * 4;
#pragma unroll
      for (int mt = 0; mt < 2; mt++)
        ldsm4(a[mt], &As[(wm * 32 + mt * 16 + (matl & 1) * 8 + mj) * ASTR + acol]);
      const int brow = ks * 8 + (lane & 3);
#pragma unroll
      for (int nt = 0; nt < 8; nt++) {
        int n = wn * 64 + nt * 8 + (lane >> 2);
        uint32_t b0 = __float_as_uint(Bs[brow * BSTR + n]);
        uint32_t b1 = __float_as_uint(Bs[(brow + 4) * BSTR + n]);
        mma8(c[0][nt], a[0], b0, b1);
        mma8(c[1][nt], a[1], b0, b1);
      }
    }
  }

#pragma unroll
  for (int mt = 0; mt < 2; mt++)
#pragma unroll
    for (int hh = 0; hh < 2; hh++) {
      int row = m0 + wm * 32 + mt * 16 + (lane >> 2) + hh * 8;
#pragma unroll
      for (int nt = 0; nt < 8; nt++) {
        int col = n0 + wn * 64 + nt * 8 + (lane & 3) * 2;
        *(float2*)&out[(size_t)row * DD + col] =
            make_float2(c[mt][nt][hh * 2], c[mt][nt][hh * 2 + 1]);
      }
    }
}

// ---------------------------------------------------------------------------
extern "C" void kernel_launch(void* const* d_in, const int* in_sizes, int n_in,
                              void* d_out, int out_size) {
  const float* x  = (const float*)d_in[0];
  const float* Wq = (const float*)d_in[1];
  const float* Wk = (const float*)d_in[2];
  const float* Wv = (const float*)d_in[3];
  const float* Wo = (const float*)d_in[4];
  float* out = (float*)d_out;

  const int attn_smem = (128 * QSTR + 128 * PSTR + 64 * VSTR) * (int)sizeof(float);  // 88064
  cudaFuncSetAttribute(attn_mma, cudaFuncAttributeMaxDynamicSharedMemorySize, attn_smem);

  qkv_mma<<<dim3(64, 8, 3), 256>>>(x, Wq, Wk, Wv);
  attn_mma<<<dim3(SS / 128, HH, BB), 256, attn_smem>>>();
  proj_mma<<<dim3(64, 8), 256>>>(Wo, out);
}

// round 9
// speedup vs baseline: 4.2532x; 1.5000x over previous
#include <cuda_runtime.h>
#include <cstdint>

#define BB 4
#define SS 2048
#define DD 1024
#define HH 16
#define DHH 64
#define NKB 32

// Scratch
__device__ float g_X[BB*SS*DD];        // tf32-rounded x
__device__ float g_Wt[3*HH*DHH*DD];    // [proj][h][n][dI] rounded, transposed, k-interleaved
__device__ float g_Wot[DD*DD];         // [n][dI]
__device__ float g_Q[BB*HH*SS*DHH];    // rounded, natural, PRE-SCALED by 0.125
__device__ float g_K[BB*HH*SS*DHH];    // rounded, dh-interleaved
__device__ float g_Vt[BB*HH*DHH*SS];   // rounded, [b,h,dh,sI] key-interleaved
__device__ float g_O[BB*HH*SS*DHH];    // rounded, natural

// ---------------------------------------------------------------------------
__device__ __forceinline__ float cvt_tf32f(float x) {
  uint32_t y;
  asm("cvt.rna.tf32.f32 %0, %1;" : "=r"(y) : "f"(x));
  return __uint_as_float(y);
}
__device__ __forceinline__ void ldsm4(uint32_t a[4], const float* p) {
  uint32_t addr = (uint32_t)__cvta_generic_to_shared(p);
  asm volatile("ldmatrix.sync.aligned.m8n8.x4.shared.b16 {%0,%1,%2,%3}, [%4];"
               : "=r"(a[0]), "=r"(a[1]), "=r"(a[2]), "=r"(a[3]) : "r"(addr));
}
__device__ __forceinline__ void mma8(float c[4], const uint32_t a[4],
                                     uint32_t b0, uint32_t b1) {
  asm volatile(
      "mma.sync.aligned.m16n8k8.row.col.f32.tf32.tf32.f32 "
      "{%0,%1,%2,%3},{%4,%5,%6,%7},{%8,%9},{%0,%1,%2,%3};"
      : "+f"(c[0]), "+f"(c[1]), "+f"(c[2]), "+f"(c[3])
      : "r"(a[0]), "r"(a[1]), "r"(a[2]), "r"(a[3]), "r"(b0), "r"(b1));
}
__device__ __forceinline__ void cpa16(uint32_t dst, const void* src) {
  asm volatile("cp.async.cg.shared.global [%0], [%1], 16;" :: "r"(dst), "l"(src));
}
#define CP_COMMIT() asm volatile("cp.async.commit_group;")
#define CP_WAIT1()  asm volatile("cp.async.wait_group 1;")

__device__ __forceinline__ int ilv(int u) {  // interleave within 8-group
  return (u & ~7) | (((u & 3) << 1) | ((u >> 2) & 1));
}

// ---------------------------------------------------------------------------
// Pre-pass: round x; round+transpose+interleave weights
// ---------------------------------------------------------------------------
__global__ void prep_x(const float* __restrict__ x) {
  int j = blockIdx.x * 256 + threadIdx.x;  // over 2M float4
  float4 v = ((const float4*)x)[j];
  ((float4*)g_X)[j] = make_float4(cvt_tf32f(v.x), cvt_tf32f(v.y),
                                  cvt_tf32f(v.z), cvt_tf32f(v.w));
}
__global__ void prep_w(const float* __restrict__ Wq, const float* __restrict__ Wk,
                       const float* __restrict__ Wv, const float* __restrict__ Wo) {
  const int N1 = 3 * HH * DD * DHH;
  int i = blockIdx.x * 256 + threadIdx.x;
  if (i < N1) {
    int p = i / (HH * DD * DHH), j = i % (HH * DD * DHH);
    int h = j / (DD * DHH), jj = j % (DD * DHH);
    int d = jj / DHH, n = jj % DHH;
    const float* W = p == 0 ? Wq : (p == 1 ? Wk : Wv);
    g_Wt[((size_t)((p * HH + h) * DHH + n)) * DD + ilv(d)] = cvt_tf32f(W[j]);
  } else {
    int k = i - N1, d = k >> 10, n = k & 1023;
    g_Wot[(size_t)n * DD + ilv(d)] = cvt_tf32f(Wo[k]);
  }
}

// ---------------------------------------------------------------------------
// QKV projection: C tile 128(M) x 128(N = 2 heads), cp.async 2-stage, LDS.64 B
// grid (64, 8, 3), block 256 (8 warps: 4M x 2N, warp 32x64)
// ---------------------------------------------------------------------------
#define SA (128*36)
#define SB (128*40)
#define STG (SA+SB)

__global__ __launch_bounds__(256, 2) void qkv_mma() {
  extern __shared__ __align__(16) float sm[];
  const int tid = threadIdx.x, lane = tid & 31, warp = tid >> 5;
  const int wm = warp >> 1, wn = warp & 1;
  const int proj = blockIdx.z, hp = blockIdx.y, m0 = blockIdx.x * 128;
  const float* Xb = g_X + (size_t)m0 * DD;
  const float* Wb = g_Wt + (size_t)((proj * HH + hp * 2) * DHH) * DD;
  uint32_t smb = (uint32_t)__cvta_generic_to_shared(sm);
  const int matl = lane >> 3, mj = lane & 7;

#pragma unroll
  for (int st = 0; st < 2; st++) {
    int k0 = st * 32;
    uint32_t ab = smb + st * STG * 4, bb = ab + SA * 4;
#pragma unroll
    for (int i = 0; i < 4; i++) {
      int cI = tid + 256 * i, r = cI >> 3, cc = cI & 7;
      cpa16(ab + (r * 36 + cc * 4) * 4, Xb + (size_t)r * DD + k0 + cc * 4);
      cpa16(bb + (r * 40 + cc * 4) * 4, Wb + (size_t)r * DD + k0 + cc * 4);
    }
    CP_COMMIT();
  }

  float c[2][8][4];
#pragma unroll
  for (int i = 0; i < 2; i++)
#pragma unroll
    for (int j = 0; j < 8; j++)
#pragma unroll
      for (int q = 0; q < 4; q++) c[i][j][q] = 0.f;

  for (int kc = 0; kc < 32; kc++) {
    CP_WAIT1();
    __syncthreads();
    const float* A = sm + (kc & 1) * STG;
    const float* B = A + SA;
#pragma unroll
    for (int ks = 0; ks < 4; ks++) {
      uint32_t a[2][4];
#pragma unroll
      for (int mt = 0; mt < 2; mt++)
        ldsm4(a[mt], &A[(wm * 32 + mt * 16 + (matl & 1) * 8 + mj) * 36 +
                        ks * 8 + (matl >> 1) * 4]);
#pragma unroll
      for (int nt = 0; nt < 8; nt++) {
        float2 b = *(const float2*)&B[(wn * 64 + nt * 8 + (lane >> 2)) * 40 +
                                      ks * 8 + (lane & 3) * 2];
        uint32_t b0 = __float_as_uint(b.x), b1 = __float_as_uint(b.y);
        mma8(c[0][nt], a[0], b0, b1);
        mma8(c[1][nt], a[1], b0, b1);
      }
    }
    __syncthreads();
    if (kc + 2 < 32) {
      int k0 = (kc + 2) * 32;
      uint32_t ab = smb + (kc & 1) * STG * 4, bb = ab + SA * 4;
#pragma unroll
      for (int i = 0; i < 4; i++) {
        int cI = tid + 256 * i, r = cI >> 3, cc = cI & 7;
        cpa16(ab + (r * 36 + cc * 4) * 4, Xb + (size_t)r * DD + k0 + cc * 4);
        cpa16(bb + (r * 40 + cc * 4) * 4, Wb + (size_t)r * DD + k0 + cc * 4);
      }
    }
    CP_COMMIT();
  }

#pragma unroll
  for (int mt = 0; mt < 2; mt++)
#pragma unroll
    for (int hh = 0; hh < 2; hh++) {
      int row = m0 + wm * 32 + mt * 16 + (lane >> 2) + hh * 8;
      int b = row >> 11, s = row & 2047;
#pragma unroll
      for (int nt = 0; nt < 8; nt++) {
        int col0 = wn * 64 + nt * 8 + (lane & 3) * 2;
        int head = hp * 2 + (col0 >> 6);
        size_t bh = (size_t)(b * HH + head);
        if (proj == 0) {
          // pre-scale Q by 1/sqrt(64); exact under tf32 rounding (power of 2)
          float v0 = cvt_tf32f(0.125f * c[mt][nt][hh * 2]);
          float v1 = cvt_tf32f(0.125f * c[mt][nt][hh * 2 + 1]);
          *(float2*)&g_Q[(bh * SS + s) * DHH + (col0 & 63)] = make_float2(v0, v1);
        } else if (proj == 1) {
          float v0 = cvt_tf32f(c[mt][nt][hh * 2]);
          float v1 = cvt_tf32f(c[mt][nt][hh * 2 + 1]);
          int d0 = col0 & 63;
          g_K[(bh * SS + s) * DHH + ilv(d0)] = v0;
          g_K[(bh * SS + s) * DHH + ilv(d0 + 1)] = v1;
        } else {
          float v0 = cvt_tf32f(c[mt][nt][hh * 2]);
          float v1 = cvt_tf32f(c[mt][nt][hh * 2 + 1]);
          int sI = ilv(s & 7) | (s & ~7);
          g_Vt[(bh * DHH + (col0 & 63)) * SS + sI] = v0;
          g_Vt[(bh * DHH + (col0 & 63) + 1) * SS + sI] = v1;
        }
      }
    }
}

// ---------------------------------------------------------------------------
// Flash attention: 128 q-rows, 64-key blocks; warp owns 16 full rows.
// K [key][dhI] LDS.64 B-frags; V [dh][keyI] LDS.64 B-frags; P smem round-trip.
// cp.async: K overlaps softmax+PV, V overlaps next S-GEMM.
// smem: Q 128*68 + K 64*72 + V 64*72 + P 128*68 = 106496 B -> 2 CTA/SM
// ---------------------------------------------------------------------------
__global__ __launch_bounds__(256, 2) void attn_mma() {
  extern __shared__ __align__(16) float sm[];
  float* Qs = sm;
  float* Ks = sm + 128 * 68;
  float* Vs = Ks + 64 * 72;
  float* Ps = Vs + 64 * 72;
  const int tid = threadIdx.x, lane = tid & 31, warp = tid >> 5;
  const int matl = lane >> 3, mj = lane & 7;
  const size_t base = ((size_t)blockIdx.z * HH + blockIdx.y) * SS * DHH;
  const int q0 = blockIdx.x * 128;
  const float* Qb = g_Q + base + (size_t)q0 * DHH;
  const float* Kb = g_K + base;
  const float* Vb = g_Vt + base;  // [dh][sI]
  float* Ob = g_O + base + (size_t)q0 * DHH;
  uint32_t smb = (uint32_t)__cvta_generic_to_shared(sm);
  uint32_t ksb = smb + 128 * 68 * 4, vsb = ksb + 64 * 72 * 4;

  // prologue: Q + K0 (group), then V0 (group)
#pragma unroll
  for (int i = 0; i < 8; i++) {
    int cI = tid + 256 * i, r = cI >> 4, cc = cI & 15;
    cpa16(smb + (r * 68 + cc * 4) * 4, Qb + (size_t)r * DHH + cc * 4);
  }
#pragma unroll
  for (int i = 0; i < 4; i++) {
    int cI = tid + 256 * i, r = cI >> 4, cc = cI & 15;
    cpa16(ksb + (r * 72 + cc * 4) * 4, Kb + (size_t)r * DHH + cc * 4);
  }
  CP_COMMIT();
#pragma unroll
  for (int i = 0; i < 4; i++) {
    int cI = tid + 256 * i, r = cI >> 4, cc = cI & 15;
    cpa16(vsb + (r * 72 + cc * 4) * 4, Vb + (size_t)r * SS + cc * 4);
  }
  CP_COMMIT();

  float o[8][4];
#pragma unroll
  for (int j = 0; j < 8; j++)
#pragma unroll
    for (int q = 0; q < 4; q++) o[j][q] = 0.f;
  float mst[2] = {-1e30f, -1e30f}, lst[2] = {0.f, 0.f};

  for (int kb = 0; kb < NKB; kb++) {
    CP_WAIT1();          // K_kb (and Q on kb=0) arrived
    __syncthreads();

    // ---- S = (Q*scale) @ K^T (Q pre-scaled in qkv epilogue) ----
    float s[8][4];
#pragma unroll
    for (int j = 0; j < 8; j++)
#pragma unroll
      for (int q = 0; q < 4; q++) s[j][q] = 0.f;
#pragma unroll
    for (int ks = 0; ks < 8; ks++) {
      uint32_t a[4];
      ldsm4(a, &Qs[(warp * 16 + (matl & 1) * 8 + mj) * 68 + ks * 8 + (matl >> 1) * 4]);
#pragma unroll
      for (int nt = 0; nt < 8; nt++) {
        float2 b = *(const float2*)&Ks[(nt * 8 + (lane >> 2)) * 72 +
                                       ks * 8 + (lane & 3) * 2];
        mma8(s[nt], a, __float_as_uint(b.x), __float_as_uint(b.y));
      }
    }
    __syncthreads();     // all warps done with Ks (and prev Ps)
    if (kb + 1 < NKB) {
#pragma unroll
      for (int i = 0; i < 4; i++) {
        int cI = tid + 256 * i, r = cI >> 4, cc = cI & 15;
        cpa16(ksb + (r * 72 + cc * 4) * 4,
              Kb + (size_t)((kb + 1) * 64 + r) * DHH + cc * 4);
      }
    }
    CP_COMMIT();

    // ---- online softmax ----
#pragma unroll
    for (int hh = 0; hh < 2; hh++) {
      float mx = s[0][hh * 2];
#pragma unroll
      for (int nt = 0; nt < 8; nt++) {
        mx = fmaxf(mx, s[nt][hh * 2]);
        mx = fmaxf(mx, s[nt][hh * 2 + 1]);
      }
      mx = fmaxf(mx, __shfl_xor_sync(0xffffffffu, mx, 1));
      mx = fmaxf(mx, __shfl_xor_sync(0xffffffffu, mx, 2));
      float mn = fmaxf(mst[hh], mx);
      float alpha = __expf(mst[hh] - mn);
      mst[hh] = mn;
      float rs = 0.f;
#pragma unroll
      for (int nt = 0; nt < 8; nt++)
#pragma unroll
        for (int q = 0; q < 2; q++) {
          float e = __expf(s[nt][hh * 2 + q] - mn);
          s[nt][hh * 2 + q] = e;
          rs += e;
        }
      rs += __shfl_xor_sync(0xffffffffu, rs, 1);
      rs += __shfl_xor_sync(0xffffffffu, rs, 2);
      lst[hh] = lst[hh] * alpha + rs;
#pragma unroll
      for (int nt = 0; nt < 8; nt++)
#pragma unroll
        for (int q = 0; q < 2; q++) o[nt][hh * 2 + q] *= alpha;
    }

    // ---- write P (tf32-rounded) ----
#pragma unroll
    for (int hh = 0; hh < 2; hh++) {
      int prow = warp * 16 + (lane >> 2) + hh * 8;
#pragma unroll
      for (int nt = 0; nt < 8; nt++) {
        int pcol = nt * 8 + (lane & 3) * 2;
        *(float2*)&Ps[prow * 68 + pcol] = make_float2(
            cvt_tf32f(s[nt][hh * 2]), cvt_tf32f(s[nt][hh * 2 + 1]));
      }
    }
    CP_WAIT1();          // V_kb arrived (K_{kb+1} may still fly)
    __syncthreads();     // P visible + V visible to all

    // ---- O += P @ V ----
#pragma unroll
    for (int ks = 0; ks < 8; ks++) {
      uint32_t a[4];
      ldsm4(a, &Ps[(warp * 16 + (matl & 1) * 8 + mj) * 68 + ks * 8 + (matl >> 1) * 4]);
#pragma unroll
      for (int nt = 0; nt < 8; nt++) {
        float2 b = *(const float2*)&Vs[(nt * 8 + (lane >> 2)) * 72 +
                                       ks * 8 + (lane & 3) * 2];
        mma8(o[nt], a, __float_as_uint(b.x), __float_as_uint(b.y));
      }
    }
    __syncthreads();     // all warps done with Vs
    if (kb + 1 < NKB) {
#pragma unroll
      for (int i = 0; i < 4; i++) {
        int cI = tid + 256 * i, r = cI >> 4, cc = cI & 15;
        cpa16(vsb + (r * 72 + cc * 4) * 4,
              Vb + (size_t)r * SS + (kb + 1) * 64 + cc * 4);
      }
    }
    CP_COMMIT();
  }

  // epilogue: normalize, round, store natural
#pragma unroll
  for (int hh = 0; hh < 2; hh++) {
    int row = warp * 16 + (lane >> 2) + hh * 8;
    float inv = 1.f / lst[hh];
#pragma unroll
    for (int nt = 0; nt < 8; nt++) {
      int col = nt * 8 + (lane & 3) * 2;
      *(float2*)&Ob[(size_t)row * DHH + col] = make_float2(
          cvt_tf32f(o[nt][hh * 2] * inv), cvt_tf32f(o[nt][hh * 2 + 1] * inv));
    }
  }
}

// ---------------------------------------------------------------------------
// Output projection: out = concat(g_O) @ Wo. Same skeleton as qkv_mma.
// grid (64, 8), block 256
// ---------------------------------------------------------------------------
__global__ __launch_bounds__(256, 2) void proj_mma(float* __restrict__ out) {
  extern __shared__ __align__(16) float sm[];
  const int tid = threadIdx.x, lane = tid & 31, warp = tid >> 5;
  const int wm = warp >> 1, wn = warp & 1;
  const int m0 = blockIdx.x * 128, n0 = blockIdx.y * 128;
  uint32_t smb = (uint32_t)__cvta_generic_to_shared(sm);
  const int matl = lane >> 3, mj = lane & 7;

#pragma unroll
  for (int st = 0; st < 2; st++) {
    int k0 = st * 32;
    uint32_t ab = smb + st * STG * 4, bb = ab + SA * 4;
#pragma unroll
    for (int i = 0; i < 4; i++) {
      int cI = tid + 256 * i, r = cI >> 3, cc = cI & 7;
      int m = m0 + r, b = m >> 11, s = m & 2047;
      int k = k0 + cc * 4;
      cpa16(ab + (r * 36 + cc * 4) * 4,
            &g_O[((size_t)(b * HH + (k >> 6)) * SS + s) * DHH + (k & 63)]);
      cpa16(bb + (r * 40 + cc * 4) * 4, &g_Wot[(size_t)(n0 + r) * DD + k]);
    }
    CP_COMMIT();
  }

  float c[2][8][4];
#pragma unroll
  for (int i = 0; i < 2; i++)
#pragma unroll
    for (int j = 0; j < 8; j++)
#pragma unroll
      for (int q = 0; q < 4; q++) c[i][j][q] = 0.f;

  for (int kc = 0; kc < 32; kc++) {
    CP_WAIT1();
    __syncthreads();
    const float* A = sm + (kc & 1) * STG;
    const float* B = A + SA;
#pragma unroll
    for (int ks = 0; ks < 4; ks++) {
      uint32_t a[2][4];
#pragma unroll
      for (int mt = 0; mt < 2; mt++)
        ldsm4(a[mt], &A[(wm * 32 + mt * 16 + (matl & 1) * 8 + mj) * 36 +
                        ks * 8 + (matl >> 1) * 4]);
#pragma unroll
      for (int nt = 0; nt < 8; nt++) {
        float2 b = *(const float2*)&B[(wn * 64 + nt * 8 + (lane >> 2)) * 40 +
                                      ks * 8 + (lane & 3) * 2];
        uint32_t b0 = __float_as_uint(b.x), b1 = __float_as_uint(b.y);
        mma8(c[0][nt], a[0], b0, b1);
        mma8(c[1][nt], a[1], b0, b1);
      }
    }
    __syncthreads();
    if (kc + 2 < 32) {
      int k0 = (kc + 2) * 32;
      uint32_t ab = smb + (kc & 1) * STG * 4, bb = ab + SA * 4;
#pragma unroll
      for (int i = 0; i < 4; i++) {
        int cI = tid + 256 * i, r = cI >> 3, cc = cI & 7;
        int m = m0 + r, b = m >> 11, s = m & 2047;
        int k = k0 + cc * 4;
        cpa16(ab + (r * 36 + cc * 4) * 4,
              &g_O[((size_t)(b * HH + (k >> 6)) * SS + s) * DHH + (k & 63)]);
        cpa16(bb + (r * 40 + cc * 4) * 4, &g_Wot[(size_t)(n0 + r) * DD + k]);
      }
    }
    CP_COMMIT();
  }

#pragma unroll
  for (int mt = 0; mt < 2; mt++)
#pragma unroll
    for (int hh = 0; hh < 2; hh++) {
      int row = m0 + wm * 32 + mt * 16 + (lane >> 2) + hh * 8;
#pragma unroll
      for (int nt = 0; nt < 8; nt++) {
        int col = n0 + wn * 64 + nt * 8 + (lane & 3) * 2;
        *(float2*)&out[(size_t)row * DD + col] =
            make_float2(c[mt][nt][hh * 2], c[mt][nt][hh * 2 + 1]);
      }
    }
}

// ---------------------------------------------------------------------------
extern "C" void kernel_launch(void* const* d_in, const int* in_sizes, int n_in,
                              void* d_out, int out_size) {
  const float* x  = (const float*)d_in[0];
  const float* Wq = (const float*)d_in[1];
  const float* Wk = (const float*)d_in[2];
  const float* Wv = (const float*)d_in[3];
  const float* Wo = (const float*)d_in[4];
  float* out = (float*)d_out;

  const int gemm_smem = STG * 2 * (int)sizeof(float);              // 77824
  const int attn_smem = (128 * 68 + 64 * 72 + 64 * 72 + 128 * 68) * (int)sizeof(float);  // 106496
  cudaFuncSetAttribute(qkv_mma, cudaFuncAttributeMaxDynamicSharedMemorySize, gemm_smem);
  cudaFuncSetAttribute(proj_mma, cudaFuncAttributeMaxDynamicSharedMemorySize, gemm_smem);
  cudaFuncSetAttribute(attn_mma, cudaFuncAttributeMaxDynamicSharedMemorySize, attn_smem);

  prep_x<<<(BB * SS * DD / 4) / 256, 256>>>(x);
  prep_w<<<(3 * HH * DD * DHH + DD * DD) / 256, 256>>>(Wq, Wk, Wv, Wo);
  qkv_mma<<<dim3(64, 8, 3), 256, gemm_smem>>>();
  attn_mma<<<dim3(SS / 128, HH, BB), 256, attn_smem>>>();
  proj_mma<<<dim3(64, 8), 256, gemm_smem>>>(out);
}